// round 6
// baseline (speedup 1.0000x reference)
#include <cuda_runtime.h>
#include <math.h>
#include <limits.h>

#define EPSV 1e-12f
#define DIMS 768
#define KMAX 8
#define TPB 256
#define WPB (TPB / 32)
#define NBLK 296                 // 148 SMs * 2 CTAs -> single wave
#define MAXCAND (NBLK * KMAX)

// Scratch (no cudaMalloc allowed)
__device__ float g_cand_val[MAXCAND];
__device__ int   g_cand_idx[MAXCAND];

// Ordering consistent with jax.lax.top_k: higher value first, lower index on ties.
__device__ __forceinline__ bool better(float v1, int i1, float v2, int i2) {
    return (v1 > v2) || (v1 == v2 && i1 < i2);
}

// ---------------------------------------------------------------------------
// Kernel 1: fused score + per-block top-k.
// Persistent grid-stride warps, q held in registers, next row prefetched
// before reducing the current row so DRAM loads are always in flight.
// ---------------------------------------------------------------------------
__global__ void __launch_bounds__(TPB)
score_topk_kernel(const float4* __restrict__ q4,
                  const float*  __restrict__ loc,
                  const float4* __restrict__ feats4,
                  const float2* __restrict__ locs2,
                  const float4* __restrict__ meta4,
                  int M, int k)
{
    const int lane   = threadIdx.x & 31;
    const int wid    = threadIdx.x >> 5;
    const int gwarp  = blockIdx.x * WPB + wid;
    const int nwarps = NBLK * WPB;

    // ---- q slice into registers (once per warp) + q-norm (once per warp) ----
    float4 b0 = __ldg(q4 + lane + 32 * 0);
    float4 b1 = __ldg(q4 + lane + 32 * 1);
    float4 b2 = __ldg(q4 + lane + 32 * 2);
    float4 b3 = __ldg(q4 + lane + 32 * 3);
    float4 b4 = __ldg(q4 + lane + 32 * 4);
    float4 b5 = __ldg(q4 + lane + 32 * 5);

    float qq = b0.x*b0.x + b0.y*b0.y + b0.z*b0.z + b0.w*b0.w
             + b1.x*b1.x + b1.y*b1.y + b1.z*b1.z + b1.w*b1.w
             + b2.x*b2.x + b2.y*b2.y + b2.z*b2.z + b2.w*b2.w
             + b3.x*b3.x + b3.y*b3.y + b3.z*b3.z + b3.w*b3.w
             + b4.x*b4.x + b4.y*b4.y + b4.z*b4.z + b4.w*b4.w
             + b5.x*b5.x + b5.y*b5.y + b5.z*b5.z + b5.w*b5.w;
    #pragma unroll
    for (int o = 16; o; o >>= 1) qq += __shfl_xor_sync(0xffffffffu, qq, o);
    const float qn = fmaxf(sqrtf(qq), EPSV);
    const float l0 = __ldg(loc);
    const float l1 = __ldg(loc + 1);

    // ---- local top-k (lane 0's registers are the meaningful copy) ----
    float lv[KMAX];
    int   li[KMAX];
    #pragma unroll
    for (int j = 0; j < KMAX; j++) { lv[j] = -INFINITY; li[j] = INT_MAX; }

    // ---- prime the pipeline: prefetch first row ----
    int row = gwarp;
    float4 a0, a1, a2, a3, a4, a5;
    float2 lrow = make_float2(0.f, 0.f);
    float4 mrow = make_float4(0.f, 0.f, 0.f, 0.f);
    if (row < M) {
        const float4* rp = feats4 + (size_t)row * (DIMS / 4);
        a0 = __ldcs(rp + lane + 32 * 0);
        a1 = __ldcs(rp + lane + 32 * 1);
        a2 = __ldcs(rp + lane + 32 * 2);
        a3 = __ldcs(rp + lane + 32 * 3);
        a4 = __ldcs(rp + lane + 32 * 4);
        a5 = __ldcs(rp + lane + 32 * 5);
        if (lane == 0) { lrow = __ldg(locs2 + row); mrow = __ldg(meta4 + row); }
    }

    while (row < M) {
        // ---- prefetch next row BEFORE reducing current (keeps DRAM busy) ----
        const int next = row + nwarps;
        float4 n0, n1, n2, n3, n4, n5;
        float2 nl = make_float2(0.f, 0.f);
        float4 nm = make_float4(0.f, 0.f, 0.f, 0.f);
        if (next < M) {
            const float4* np = feats4 + (size_t)next * (DIMS / 4);
            n0 = __ldcs(np + lane + 32 * 0);
            n1 = __ldcs(np + lane + 32 * 1);
            n2 = __ldcs(np + lane + 32 * 2);
            n3 = __ldcs(np + lane + 32 * 3);
            n4 = __ldcs(np + lane + 32 * 4);
            n5 = __ldcs(np + lane + 32 * 5);
            if (lane == 0) { nl = __ldg(locs2 + next); nm = __ldg(meta4 + next); }
        }

        // ---- dot & sum-of-squares for current row ----
        float dot = a0.x*b0.x + a0.y*b0.y + a0.z*b0.z + a0.w*b0.w
                  + a1.x*b1.x + a1.y*b1.y + a1.z*b1.z + a1.w*b1.w
                  + a2.x*b2.x + a2.y*b2.y + a2.z*b2.z + a2.w*b2.w
                  + a3.x*b3.x + a3.y*b3.y + a3.z*b3.z + a3.w*b3.w
                  + a4.x*b4.x + a4.y*b4.y + a4.z*b4.z + a4.w*b4.w
                  + a5.x*b5.x + a5.y*b5.y + a5.z*b5.z + a5.w*b5.w;
        float ss  = a0.x*a0.x + a0.y*a0.y + a0.z*a0.z + a0.w*a0.w
                  + a1.x*a1.x + a1.y*a1.y + a1.z*a1.z + a1.w*a1.w
                  + a2.x*a2.x + a2.y*a2.y + a2.z*a2.z + a2.w*a2.w
                  + a3.x*a3.x + a3.y*a3.y + a3.z*a3.z + a3.w*a3.w
                  + a4.x*a4.x + a4.y*a4.y + a4.z*a4.z + a4.w*a4.w
                  + a5.x*a5.x + a5.y*a5.y + a5.z*a5.z + a5.w*a5.w;
        #pragma unroll
        for (int o = 16; o; o >>= 1) {
            dot += __shfl_xor_sync(0xffffffffu, dot, o);
            ss  += __shfl_xor_sync(0xffffffffu, ss,  o);
        }

        if (lane == 0) {
            float sim = dot / (fmaxf(sqrtf(ss), EPSV) * qn);

            float dx = lrow.x - l0;
            float dy = lrow.y - l1;
            float spatial = 1.f / (1.f + sqrtf(dx * dx + dy * dy));

            // exp(-(3600 - ts)/3600) == exp(ts/3600 - 1)
            float temporal = expf(mrow.y * (1.f / 3600.f) - 1.f);

            float s = (0.5f * sim + 0.3f * spatial + 0.2f * temporal) * mrow.x;

            if (better(s, row, lv[k - 1], li[k - 1])) {
                int j = k - 1;
                while (j > 0 && better(s, row, lv[j - 1], li[j - 1])) {
                    lv[j] = lv[j - 1]; li[j] = li[j - 1]; --j;
                }
                lv[j] = s; li[j] = row;
            }
        }

        a0 = n0; a1 = n1; a2 = n2; a3 = n3; a4 = n4; a5 = n5;
        lrow = nl; mrow = nm;
        row = next;
    }

    // ---- block merge: warps -> shared -> thread 0 serial merge (<=64 entries) ----
    __shared__ float s_val[WPB * KMAX];
    __shared__ int   s_idx[WPB * KMAX];
    if (lane == 0) {
        for (int j = 0; j < k; j++) {
            s_val[wid * k + j] = lv[j];
            s_idx[wid * k + j] = li[j];
        }
    }
    __syncthreads();

    if (threadIdx.x == 0) {
        float bv[KMAX];
        int   bi[KMAX];
        #pragma unroll
        for (int j = 0; j < KMAX; j++) { bv[j] = -INFINITY; bi[j] = INT_MAX; }
        const int total = WPB * k;
        for (int p = 0; p < total; p++) {
            float v = s_val[p];
            int   i = s_idx[p];
            if (better(v, i, bv[k - 1], bi[k - 1])) {
                int j = k - 1;
                while (j > 0 && better(v, i, bv[j - 1], bi[j - 1])) {
                    bv[j] = bv[j - 1]; bi[j] = bi[j - 1]; --j;
                }
                bv[j] = v; bi[j] = i;
            }
        }
        for (int j = 0; j < k; j++) {
            g_cand_val[blockIdx.x * k + j] = bv[j];
            g_cand_idx[blockIdx.x * k + j] = bi[j];
        }
    }
}

// ---------------------------------------------------------------------------
// Kernel 2: final top-k over block candidates; writes [scores | indices].
// ---------------------------------------------------------------------------
__global__ void __launch_bounds__(TPB)
topk_final(int ncand, int k, float* __restrict__ out)
{
    __shared__ float s_val[MAXCAND];
    __shared__ int   s_idx[MAXCAND];
    __shared__ float s_rv[TPB / 32];
    __shared__ int   s_ri[TPB / 32];
    __shared__ int   s_rp[TPB / 32];

    for (int p = threadIdx.x; p < ncand; p += TPB) {
        s_val[p] = g_cand_val[p];
        s_idx[p] = g_cand_idx[p];
    }
    __syncthreads();

    const int wid  = threadIdx.x >> 5;
    const int lane = threadIdx.x & 31;

    for (int sel = 0; sel < k; sel++) {
        float bv = -INFINITY; int bi = INT_MAX; int bp = -1;
        for (int p = threadIdx.x; p < ncand; p += TPB) {
            if (better(s_val[p], s_idx[p], bv, bi)) { bv = s_val[p]; bi = s_idx[p]; bp = p; }
        }
        #pragma unroll
        for (int o = 16; o; o >>= 1) {
            float ov = __shfl_xor_sync(0xffffffffu, bv, o);
            int   oi = __shfl_xor_sync(0xffffffffu, bi, o);
            int   op = __shfl_xor_sync(0xffffffffu, bp, o);
            if (better(ov, oi, bv, bi)) { bv = ov; bi = oi; bp = op; }
        }
        if (lane == 0) { s_rv[wid] = bv; s_ri[wid] = bi; s_rp[wid] = bp; }
        __syncthreads();
        if (threadIdx.x == 0) {
            bv = s_rv[0]; bi = s_ri[0]; bp = s_rp[0];
            #pragma unroll
            for (int w = 1; w < TPB / 32; w++)
                if (better(s_rv[w], s_ri[w], bv, bi)) { bv = s_rv[w]; bi = s_ri[w]; bp = s_rp[w]; }
            out[sel]     = bv;              // top_scores
            out[k + sel] = (float)bi;       // top_indices (exact in fp32 for idx < 2^24)
            if (bp >= 0) { s_val[bp] = -INFINITY; s_idx[bp] = INT_MAX; }
        }
        __syncthreads();
    }
}

// ---------------------------------------------------------------------------
// Launch
// ---------------------------------------------------------------------------
extern "C" void kernel_launch(void* const* d_in, const int* in_sizes, int n_in,
                              void* d_out, int out_size)
{
    const float* q     = (const float*)d_in[0];   // (768,)
    const float* loc   = (const float*)d_in[1];   // (2,)
    const float* feats = (const float*)d_in[2];   // (M, 768)
    const float* locs  = (const float*)d_in[3];   // (M, 2)
    const float* meta  = (const float*)d_in[4];   // (M, 4)
    float* out = (float*)d_out;                   // [k scores | k indices]

    int M = in_sizes[2] / DIMS;
    int k = out_size / 2;
    if (k < 1) k = 1;
    if (k > KMAX) k = KMAX;

    score_topk_kernel<<<NBLK, TPB>>>((const float4*)q, loc,
                                     (const float4*)feats,
                                     (const float2*)locs,
                                     (const float4*)meta, M, k);
    topk_final<<<1, TPB>>>(NBLK * k, k, out);
}

// round 7
// speedup vs baseline: 1.0203x; 1.0203x over previous
#include <cuda_runtime.h>
#include <math.h>
#include <limits.h>

#define EPSV 1e-12f
#define DIMS 768
#define MAXM (131072)
#define KMAX 8
#define NBLK_T 128               // tail-kernel blocks
#define TPB 256

// Scratch (no cudaMalloc allowed)
__device__ float g_scores[MAXM];
__device__ float g_cand_val[NBLK_T * KMAX];
__device__ int   g_cand_idx[NBLK_T * KMAX];
__device__ unsigned int g_done = 0;   // last-block-done counter (reset each run)

// Ordering consistent with jax.lax.top_k: higher value first, lower index on ties.
__device__ __forceinline__ bool better(float v1, int i1, float v2, int i2) {
    return (v1 > v2) || (v1 == v2 && i1 < i2);
}

// ---------------------------------------------------------------------------
// Kernel 1: fused scoring, one warp per memory row. Barrier-free (R5 proven).
// ---------------------------------------------------------------------------
__global__ void __launch_bounds__(TPB)
score_kernel(const float4* __restrict__ q4,
             const float*  __restrict__ loc,
             const float4* __restrict__ feats4,
             const float2* __restrict__ locs2,
             const float4* __restrict__ meta4,
             int M)
{
    const int wid  = threadIdx.x >> 5;
    const int lane = threadIdx.x & 31;
    const int row  = blockIdx.x * (TPB / 32) + wid;
    if (row >= M) return;

    // Issue epilogue loads early so their latency hides under the feats stream.
    float2 lrow = make_float2(0.f, 0.f);
    float4 mrow = make_float4(0.f, 0.f, 0.f, 0.f);
    float  l0 = 0.f, l1 = 0.f;
    if (lane == 0) {
        lrow = __ldg(locs2 + row);
        mrow = __ldg(meta4 + row);
        l0 = __ldg(loc);
        l1 = __ldg(loc + 1);
    }

    const float4* __restrict__ rp = feats4 + (size_t)row * (DIMS / 4);

    // Batch all 6 row loads up-front (MLP=6/warp), streaming hint (read-once).
    float4 a0 = __ldcs(rp + lane + 32 * 0);
    float4 a1 = __ldcs(rp + lane + 32 * 1);
    float4 a2 = __ldcs(rp + lane + 32 * 2);
    float4 a3 = __ldcs(rp + lane + 32 * 3);
    float4 a4 = __ldcs(rp + lane + 32 * 4);
    float4 a5 = __ldcs(rp + lane + 32 * 5);

    float dot = 0.f, ss = 0.f, qq = 0.f;
    {
        float4 b;
        b = __ldg(q4 + lane + 32 * 0);
        dot += a0.x*b.x + a0.y*b.y + a0.z*b.z + a0.w*b.w;
        ss  += a0.x*a0.x + a0.y*a0.y + a0.z*a0.z + a0.w*a0.w;
        qq  += b.x*b.x + b.y*b.y + b.z*b.z + b.w*b.w;
        b = __ldg(q4 + lane + 32 * 1);
        dot += a1.x*b.x + a1.y*b.y + a1.z*b.z + a1.w*b.w;
        ss  += a1.x*a1.x + a1.y*a1.y + a1.z*a1.z + a1.w*a1.w;
        qq  += b.x*b.x + b.y*b.y + b.z*b.z + b.w*b.w;
        b = __ldg(q4 + lane + 32 * 2);
        dot += a2.x*b.x + a2.y*b.y + a2.z*b.z + a2.w*b.w;
        ss  += a2.x*a2.x + a2.y*a2.y + a2.z*a2.z + a2.w*a2.w;
        qq  += b.x*b.x + b.y*b.y + b.z*b.z + b.w*b.w;
        b = __ldg(q4 + lane + 32 * 3);
        dot += a3.x*b.x + a3.y*b.y + a3.z*b.z + a3.w*b.w;
        ss  += a3.x*a3.x + a3.y*a3.y + a3.z*a3.z + a3.w*a3.w;
        qq  += b.x*b.x + b.y*b.y + b.z*b.z + b.w*b.w;
        b = __ldg(q4 + lane + 32 * 4);
        dot += a4.x*b.x + a4.y*b.y + a4.z*b.z + a4.w*b.w;
        ss  += a4.x*a4.x + a4.y*a4.y + a4.z*a4.z + a4.w*a4.w;
        qq  += b.x*b.x + b.y*b.y + b.z*b.z + b.w*b.w;
        b = __ldg(q4 + lane + 32 * 5);
        dot += a5.x*b.x + a5.y*b.y + a5.z*b.z + a5.w*b.w;
        ss  += a5.x*a5.x + a5.y*a5.y + a5.z*a5.z + a5.w*a5.w;
        qq  += b.x*b.x + b.y*b.y + b.z*b.z + b.w*b.w;
    }

    #pragma unroll
    for (int o = 16; o; o >>= 1) {
        dot += __shfl_xor_sync(0xffffffffu, dot, o);
        ss  += __shfl_xor_sync(0xffffffffu, ss,  o);
        qq  += __shfl_xor_sync(0xffffffffu, qq,  o);
    }

    if (lane == 0) {
        float qn = fmaxf(sqrtf(qq), EPSV);
        float mn = fmaxf(sqrtf(ss), EPSV);
        float sim = dot / (mn * qn);

        float dx = lrow.x - l0;
        float dy = lrow.y - l1;
        float spatial = 1.f / (1.f + sqrtf(dx * dx + dy * dy));

        // exp(-(3600 - ts)/3600) == exp(ts/3600 - 1)
        float temporal = expf(mrow.y * (1.f / 3600.f) - 1.f);

        g_scores[row] = (0.5f * sim + 0.3f * spatial + 0.2f * temporal) * mrow.x;
    }
}

// ---------------------------------------------------------------------------
// Kernel 2: single-launch top-k. Each block does a partial top-k over its
// slice of g_scores and writes k candidates; the LAST block to finish merges
// all candidates and writes the output. (last-block-done pattern; counter is
// reset by the last block so every graph replay is identical.)
// ---------------------------------------------------------------------------
__global__ void __launch_bounds__(TPB)
topk_tail(int M, int k, float* __restrict__ out)
{
    __shared__ float s_val[TPB * KMAX];
    __shared__ int   s_idx[TPB * KMAX];
    __shared__ float s_rv[TPB / 32];
    __shared__ int   s_ri[TPB / 32];
    __shared__ int   s_rp[TPB / 32];
    __shared__ bool  s_last;

    const int wid  = threadIdx.x >> 5;
    const int lane = threadIdx.x & 31;

    // ---- phase 1: per-thread local top-k over grid-stride float4 slice ----
    float lv[KMAX];
    int   li[KMAX];
    #pragma unroll
    for (int j = 0; j < KMAX; j++) { lv[j] = -INFINITY; li[j] = INT_MAX; }

    const float4* sc4 = (const float4*)g_scores;
    const int n4 = M >> 2;
    for (int i = blockIdx.x * TPB + threadIdx.x; i < n4; i += NBLK_T * TPB) {
        float4 v = sc4[i];
        const int base = 4 * i;
        #pragma unroll
        for (int c = 0; c < 4; c++) {
            float vc = (c == 0) ? v.x : (c == 1) ? v.y : (c == 2) ? v.z : v.w;
            int   ic = base + c;
            if (better(vc, ic, lv[k - 1], li[k - 1])) {
                int j = k - 1;
                while (j > 0 && better(vc, ic, lv[j - 1], li[j - 1])) {
                    lv[j] = lv[j - 1]; li[j] = li[j - 1]; --j;
                }
                lv[j] = vc; li[j] = ic;
            }
        }
    }
    // remainder elements (M not multiple of 4)
    if (blockIdx.x == 0) {
        int rbase = n4 << 2;
        int i = rbase + threadIdx.x;
        if (i < M) {
            float vc = g_scores[i];
            if (better(vc, i, lv[k - 1], li[k - 1])) {
                int j = k - 1;
                while (j > 0 && better(vc, i, lv[j - 1], li[j - 1])) {
                    lv[j] = lv[j - 1]; li[j] = li[j - 1]; --j;
                }
                lv[j] = vc; li[j] = i;
            }
        }
    }

    for (int j = 0; j < k; j++) {
        s_val[threadIdx.x * k + j] = lv[j];
        s_idx[threadIdx.x * k + j] = li[j];
    }
    __syncthreads();

    // ---- phase 2: block merge via k selection passes, write candidates ----
    const int total = TPB * k;
    for (int sel = 0; sel < k; sel++) {
        float bv = -INFINITY; int bi = INT_MAX; int bp = -1;
        for (int p = threadIdx.x; p < total; p += TPB) {
            if (better(s_val[p], s_idx[p], bv, bi)) { bv = s_val[p]; bi = s_idx[p]; bp = p; }
        }
        #pragma unroll
        for (int o = 16; o; o >>= 1) {
            float ov = __shfl_xor_sync(0xffffffffu, bv, o);
            int   oi = __shfl_xor_sync(0xffffffffu, bi, o);
            int   op = __shfl_xor_sync(0xffffffffu, bp, o);
            if (better(ov, oi, bv, bi)) { bv = ov; bi = oi; bp = op; }
        }
        if (lane == 0) { s_rv[wid] = bv; s_ri[wid] = bi; s_rp[wid] = bp; }
        __syncthreads();
        if (threadIdx.x == 0) {
            bv = s_rv[0]; bi = s_ri[0]; bp = s_rp[0];
            #pragma unroll
            for (int w = 1; w < TPB / 32; w++)
                if (better(s_rv[w], s_ri[w], bv, bi)) { bv = s_rv[w]; bi = s_ri[w]; bp = s_rp[w]; }
            g_cand_val[blockIdx.x * k + sel] = bv;
            g_cand_idx[blockIdx.x * k + sel] = bi;
            if (bp >= 0) { s_val[bp] = -INFINITY; s_idx[bp] = INT_MAX; }
        }
        __syncthreads();
    }

    // ---- phase 3: last block merges all candidates ----
    if (threadIdx.x == 0) {
        __threadfence();                       // publish this block's candidates
        unsigned int t = atomicAdd(&g_done, 1u);
        s_last = (t == (unsigned int)(gridDim.x - 1));
    }
    __syncthreads();
    if (!s_last) return;
    __threadfence();

    const int ncand = gridDim.x * k;           // <= 1024
    for (int p = threadIdx.x; p < ncand; p += TPB) {
        s_val[p] = __ldcg(&g_cand_val[p]);     // bypass L1: written by other SMs
        s_idx[p] = __ldcg(&g_cand_idx[p]);
    }
    __syncthreads();

    for (int sel = 0; sel < k; sel++) {
        float bv = -INFINITY; int bi = INT_MAX; int bp = -1;
        for (int p = threadIdx.x; p < ncand; p += TPB) {
            if (better(s_val[p], s_idx[p], bv, bi)) { bv = s_val[p]; bi = s_idx[p]; bp = p; }
        }
        #pragma unroll
        for (int o = 16; o; o >>= 1) {
            float ov = __shfl_xor_sync(0xffffffffu, bv, o);
            int   oi = __shfl_xor_sync(0xffffffffu, bi, o);
            int   op = __shfl_xor_sync(0xffffffffu, bp, o);
            if (better(ov, oi, bv, bi)) { bv = ov; bi = oi; bp = op; }
        }
        if (lane == 0) { s_rv[wid] = bv; s_ri[wid] = bi; s_rp[wid] = bp; }
        __syncthreads();
        if (threadIdx.x == 0) {
            bv = s_rv[0]; bi = s_ri[0]; bp = s_rp[0];
            #pragma unroll
            for (int w = 1; w < TPB / 32; w++)
                if (better(s_rv[w], s_ri[w], bv, bi)) { bv = s_rv[w]; bi = s_ri[w]; bp = s_rp[w]; }
            out[sel]     = bv;              // top_scores
            out[k + sel] = (float)bi;       // top_indices (exact in fp32 for idx < 2^24)
            if (bp >= 0) { s_val[bp] = -INFINITY; s_idx[bp] = INT_MAX; }
        }
        __syncthreads();
    }

    if (threadIdx.x == 0) g_done = 0;          // reset for next graph replay
}

// ---------------------------------------------------------------------------
// Launch
// ---------------------------------------------------------------------------
extern "C" void kernel_launch(void* const* d_in, const int* in_sizes, int n_in,
                              void* d_out, int out_size)
{
    const float* q     = (const float*)d_in[0];   // (768,)
    const float* loc   = (const float*)d_in[1];   // (2,)
    const float* feats = (const float*)d_in[2];   // (M, 768)
    const float* locs  = (const float*)d_in[3];   // (M, 2)
    const float* meta  = (const float*)d_in[4];   // (M, 4)
    float* out = (float*)d_out;                   // [k scores | k indices]

    int M = in_sizes[2] / DIMS;
    if (M > MAXM) M = MAXM;
    int k = out_size / 2;
    if (k < 1) k = 1;
    if (k > KMAX) k = KMAX;

    const int warps_per_block = TPB / 32;
    const int nblk_score = (M + warps_per_block - 1) / warps_per_block;

    score_kernel<<<nblk_score, TPB>>>((const float4*)q, loc,
                                      (const float4*)feats,
                                      (const float2*)locs,
                                      (const float4*)meta, M);
    topk_tail<<<NBLK_T, TPB>>>(M, k, out);
}

// round 8
// speedup vs baseline: 1.0570x; 1.0360x over previous
#include <cuda_runtime.h>
#include <math.h>
#include <limits.h>

#define EPSV 1e-12f
#define DIMS 768
#define MAXM (131072)
#define KMAX 8
#define NBLK_T 148               // >=148: dodge low-grid issue throttle; single wave
#define TPB 256

// Scratch (no cudaMalloc allowed)
__device__ float g_scores[MAXM];
__device__ float g_cand_val[NBLK_T * KMAX];
__device__ int   g_cand_idx[NBLK_T * KMAX];
__device__ unsigned int g_done = 0;   // last-block-done counter (reset each run)

// Ordering consistent with jax.lax.top_k: higher value first, lower index on ties.
__device__ __forceinline__ bool better(float v1, int i1, float v2, int i2) {
    return (v1 > v2) || (v1 == v2 && i1 < i2);
}

// Branchless sorted-insert into a register-resident descending top-K list.
// All indices compile-time -> stays in registers (no LDL/STL).
template<int K>
__device__ __forceinline__ void insertK(float (&lv)[K], int (&li)[K], float v, int i) {
    if (!better(v, i, lv[K - 1], li[K - 1])) return;
    bool b[K];
    #pragma unroll
    for (int j = 0; j < K; j++) b[j] = better(lv[j], li[j], v, i);
    #pragma unroll
    for (int j = K - 1; j >= 1; --j) {
        lv[j] = b[j] ? lv[j] : (b[j - 1] ? v : lv[j - 1]);
        li[j] = b[j] ? li[j] : (b[j - 1] ? i : li[j - 1]);
    }
    if (!b[0]) { lv[0] = v; li[0] = i; }
}

// ---------------------------------------------------------------------------
// Kernel 1: fused scoring, one warp per memory row. Barrier-free (proven).
// ---------------------------------------------------------------------------
__global__ void __launch_bounds__(TPB)
score_kernel(const float4* __restrict__ q4,
             const float*  __restrict__ loc,
             const float4* __restrict__ feats4,
             const float2* __restrict__ locs2,
             const float4* __restrict__ meta4,
             int M)
{
    const int wid  = threadIdx.x >> 5;
    const int lane = threadIdx.x & 31;
    const int row  = blockIdx.x * (TPB / 32) + wid;
    if (row >= M) return;

    float2 lrow = make_float2(0.f, 0.f);
    float4 mrow = make_float4(0.f, 0.f, 0.f, 0.f);
    float  l0 = 0.f, l1 = 0.f;
    if (lane == 0) {
        lrow = __ldg(locs2 + row);
        mrow = __ldg(meta4 + row);
        l0 = __ldg(loc);
        l1 = __ldg(loc + 1);
    }

    const float4* __restrict__ rp = feats4 + (size_t)row * (DIMS / 4);

    float4 a0 = __ldcs(rp + lane + 32 * 0);
    float4 a1 = __ldcs(rp + lane + 32 * 1);
    float4 a2 = __ldcs(rp + lane + 32 * 2);
    float4 a3 = __ldcs(rp + lane + 32 * 3);
    float4 a4 = __ldcs(rp + lane + 32 * 4);
    float4 a5 = __ldcs(rp + lane + 32 * 5);

    float dot = 0.f, ss = 0.f, qq = 0.f;
    {
        float4 b;
        b = __ldg(q4 + lane + 32 * 0);
        dot += a0.x*b.x + a0.y*b.y + a0.z*b.z + a0.w*b.w;
        ss  += a0.x*a0.x + a0.y*a0.y + a0.z*a0.z + a0.w*a0.w;
        qq  += b.x*b.x + b.y*b.y + b.z*b.z + b.w*b.w;
        b = __ldg(q4 + lane + 32 * 1);
        dot += a1.x*b.x + a1.y*b.y + a1.z*b.z + a1.w*b.w;
        ss  += a1.x*a1.x + a1.y*a1.y + a1.z*a1.z + a1.w*a1.w;
        qq  += b.x*b.x + b.y*b.y + b.z*b.z + b.w*b.w;
        b = __ldg(q4 + lane + 32 * 2);
        dot += a2.x*b.x + a2.y*b.y + a2.z*b.z + a2.w*b.w;
        ss  += a2.x*a2.x + a2.y*a2.y + a2.z*a2.z + a2.w*a2.w;
        qq  += b.x*b.x + b.y*b.y + b.z*b.z + b.w*b.w;
        b = __ldg(q4 + lane + 32 * 3);
        dot += a3.x*b.x + a3.y*b.y + a3.z*b.z + a3.w*b.w;
        ss  += a3.x*a3.x + a3.y*a3.y + a3.z*a3.z + a3.w*a3.w;
        qq  += b.x*b.x + b.y*b.y + b.z*b.z + b.w*b.w;
        b = __ldg(q4 + lane + 32 * 4);
        dot += a4.x*b.x + a4.y*b.y + a4.z*b.z + a4.w*b.w;
        ss  += a4.x*a4.x + a4.y*a4.y + a4.z*a4.z + a4.w*a4.w;
        qq  += b.x*b.x + b.y*b.y + b.z*b.z + b.w*b.w;
        b = __ldg(q4 + lane + 32 * 5);
        dot += a5.x*b.x + a5.y*b.y + a5.z*b.z + a5.w*b.w;
        ss  += a5.x*a5.x + a5.y*a5.y + a5.z*a5.z + a5.w*a5.w;
        qq  += b.x*b.x + b.y*b.y + b.z*b.z + b.w*b.w;
    }

    #pragma unroll
    for (int o = 16; o; o >>= 1) {
        dot += __shfl_xor_sync(0xffffffffu, dot, o);
        ss  += __shfl_xor_sync(0xffffffffu, ss,  o);
        qq  += __shfl_xor_sync(0xffffffffu, qq,  o);
    }

    if (lane == 0) {
        float qn = fmaxf(sqrtf(qq), EPSV);
        float mn = fmaxf(sqrtf(ss), EPSV);
        float sim = dot / (mn * qn);

        float dx = lrow.x - l0;
        float dy = lrow.y - l1;
        float spatial = 1.f / (1.f + sqrtf(dx * dx + dy * dy));

        // exp(-(3600 - ts)/3600) == exp(ts/3600 - 1)
        float temporal = expf(mrow.y * (1.f / 3600.f) - 1.f);

        g_scores[row] = (0.5f * sim + 0.3f * spatial + 0.2f * temporal) * mrow.x;
    }
}

// ---------------------------------------------------------------------------
// Kernel 2: single-launch top-k, templated on K (register-resident lists).
// Each block top-k's its slice; the LAST block merges all candidates.
// ---------------------------------------------------------------------------
template<int K>
__global__ void __launch_bounds__(TPB)
topk_tail(int M, float* __restrict__ out)
{
    __shared__ float s_val[TPB * K];
    __shared__ int   s_idx[TPB * K];
    __shared__ float s_rv[TPB / 32];
    __shared__ int   s_ri[TPB / 32];
    __shared__ int   s_rp[TPB / 32];
    __shared__ bool  s_last;

    const int wid  = threadIdx.x >> 5;
    const int lane = threadIdx.x & 31;

    // ---- phase 1: per-thread register top-K over grid-stride float4 slice ----
    float lv[K];
    int   li[K];
    #pragma unroll
    for (int j = 0; j < K; j++) { lv[j] = -INFINITY; li[j] = INT_MAX; }

    const float4* sc4 = (const float4*)g_scores;
    const int n4 = M >> 2;
    for (int i = blockIdx.x * TPB + threadIdx.x; i < n4; i += NBLK_T * TPB) {
        float4 v = sc4[i];
        const int base = 4 * i;
        insertK<K>(lv, li, v.x, base + 0);
        insertK<K>(lv, li, v.y, base + 1);
        insertK<K>(lv, li, v.z, base + 2);
        insertK<K>(lv, li, v.w, base + 3);
    }
    if (blockIdx.x == 0) {                     // M % 4 remainder
        int i = (n4 << 2) + threadIdx.x;
        if (i < M) insertK<K>(lv, li, g_scores[i], i);
    }

    #pragma unroll
    for (int j = 0; j < K; j++) {
        s_val[threadIdx.x * K + j] = lv[j];
        s_idx[threadIdx.x * K + j] = li[j];
    }
    __syncthreads();

    // ---- phase 2: block merge via K selection passes, write candidates ----
    const int total = TPB * K;
    #pragma unroll 1
    for (int sel = 0; sel < K; sel++) {
        float bv = -INFINITY; int bi = INT_MAX; int bp = -1;
        for (int p = threadIdx.x; p < total; p += TPB) {
            if (better(s_val[p], s_idx[p], bv, bi)) { bv = s_val[p]; bi = s_idx[p]; bp = p; }
        }
        #pragma unroll
        for (int o = 16; o; o >>= 1) {
            float ov = __shfl_xor_sync(0xffffffffu, bv, o);
            int   oi = __shfl_xor_sync(0xffffffffu, bi, o);
            int   op = __shfl_xor_sync(0xffffffffu, bp, o);
            if (better(ov, oi, bv, bi)) { bv = ov; bi = oi; bp = op; }
        }
        if (lane == 0) { s_rv[wid] = bv; s_ri[wid] = bi; s_rp[wid] = bp; }
        __syncthreads();
        if (threadIdx.x == 0) {
            bv = s_rv[0]; bi = s_ri[0]; bp = s_rp[0];
            #pragma unroll
            for (int w = 1; w < TPB / 32; w++)
                if (better(s_rv[w], s_ri[w], bv, bi)) { bv = s_rv[w]; bi = s_ri[w]; bp = s_rp[w]; }
            g_cand_val[blockIdx.x * K + sel] = bv;
            g_cand_idx[blockIdx.x * K + sel] = bi;
            if (bp >= 0) { s_val[bp] = -INFINITY; s_idx[bp] = INT_MAX; }
        }
        __syncthreads();
    }

    // ---- phase 3: last block merges all candidates ----
    if (threadIdx.x == 0) {
        __threadfence();                       // publish this block's candidates
        unsigned int t = atomicAdd(&g_done, 1u);
        s_last = (t == (unsigned int)(gridDim.x - 1));
    }
    __syncthreads();
    if (!s_last) return;
    __threadfence();

    const int ncand = NBLK_T * K;              // 148*K <= 1184
    // per-thread register top-K over candidates (ncand/TPB ~= 3-5 each)
    #pragma unroll
    for (int j = 0; j < K; j++) { lv[j] = -INFINITY; li[j] = INT_MAX; }
    for (int p = threadIdx.x; p < ncand; p += TPB)
        insertK<K>(lv, li, __ldcg(&g_cand_val[p]), __ldcg(&g_cand_idx[p]));

    #pragma unroll
    for (int j = 0; j < K; j++) {
        s_val[threadIdx.x * K + j] = lv[j];
        s_idx[threadIdx.x * K + j] = li[j];
    }
    __syncthreads();

    #pragma unroll 1
    for (int sel = 0; sel < K; sel++) {
        float bv = -INFINITY; int bi = INT_MAX; int bp = -1;
        for (int p = threadIdx.x; p < total; p += TPB) {
            if (better(s_val[p], s_idx[p], bv, bi)) { bv = s_val[p]; bi = s_idx[p]; bp = p; }
        }
        #pragma unroll
        for (int o = 16; o; o >>= 1) {
            float ov = __shfl_xor_sync(0xffffffffu, bv, o);
            int   oi = __shfl_xor_sync(0xffffffffu, bi, o);
            int   op = __shfl_xor_sync(0xffffffffu, bp, o);
            if (better(ov, oi, bv, bi)) { bv = ov; bi = oi; bp = op; }
        }
        if (lane == 0) { s_rv[wid] = bv; s_ri[wid] = bi; s_rp[wid] = bp; }
        __syncthreads();
        if (threadIdx.x == 0) {
            bv = s_rv[0]; bi = s_ri[0]; bp = s_rp[0];
            #pragma unroll
            for (int w = 1; w < TPB / 32; w++)
                if (better(s_rv[w], s_ri[w], bv, bi)) { bv = s_rv[w]; bi = s_ri[w]; bp = s_rp[w]; }
            out[sel]     = bv;              // top_scores
            out[K + sel] = (float)bi;       // top_indices (exact in fp32 for idx < 2^24)
            if (bp >= 0) { s_val[bp] = -INFINITY; s_idx[bp] = INT_MAX; }
        }
        __syncthreads();
    }

    if (threadIdx.x == 0) g_done = 0;          // reset for next graph replay
}

// ---------------------------------------------------------------------------
// Launch
// ---------------------------------------------------------------------------
extern "C" void kernel_launch(void* const* d_in, const int* in_sizes, int n_in,
                              void* d_out, int out_size)
{
    const float* q     = (const float*)d_in[0];   // (768,)
    const float* loc   = (const float*)d_in[1];   // (2,)
    const float* feats = (const float*)d_in[2];   // (M, 768)
    const float* locs  = (const float*)d_in[3];   // (M, 2)
    const float* meta  = (const float*)d_in[4];   // (M, 4)
    float* out = (float*)d_out;                   // [k scores | k indices]

    int M = in_sizes[2] / DIMS;
    if (M > MAXM) M = MAXM;
    int k = out_size / 2;
    if (k < 1) k = 1;
    if (k > KMAX) k = KMAX;

    const int warps_per_block = TPB / 32;
    const int nblk_score = (M + warps_per_block - 1) / warps_per_block;

    score_kernel<<<nblk_score, TPB>>>((const float4*)q, loc,
                                      (const float4*)feats,
                                      (const float2*)locs,
                                      (const float4*)meta, M);

    switch (k) {
        case 1: topk_tail<1><<<NBLK_T, TPB>>>(M, out); break;
        case 2: topk_tail<2><<<NBLK_T, TPB>>>(M, out); break;
        case 3: topk_tail<3><<<NBLK_T, TPB>>>(M, out); break;
        case 4: topk_tail<4><<<NBLK_T, TPB>>>(M, out); break;
        case 5: topk_tail<5><<<NBLK_T, TPB>>>(M, out); break;
        case 6: topk_tail<6><<<NBLK_T, TPB>>>(M, out); break;
        case 7: topk_tail<7><<<NBLK_T, TPB>>>(M, out); break;
        default: topk_tail<8><<<NBLK_T, TPB>>>(M, out); break;
    }
}